// round 15
// baseline (speedup 1.0000x reference)
#include <cuda_runtime.h>
#include <cuda_bf16.h>

// Fixed shapes from reference setup_inputs
#define NPTS 8192
#define TPB  128                     // threads per CTA (2 i-points per thread)
#define TILE 256                     // i-tile edge
#define JC   128                     // j-chunk per CTA
#define NTILES (NPTS / TILE)         // 32
#define NTRI (NTILES * (NTILES + 1) / 2)   // 528 triangular tiles
#define NBLK (NTRI * 2)              // 1056 CTAs

__device__ float g_partials[NBLK];
__device__ unsigned int g_count;     // zero at load; self-reset each launch

// A&S 7.1.25 (3-term, |eps| <= 2.5e-5), x = r/sqrt(2) folded into p
#define P3S  0.3326701f              // 0.47047 / sqrt(2)
#define A1c  0.3480242f
#define A2c  (-0.0958798f)
#define A3c  0.7478556f
#define NEG_HALF_LOG2E (-0.7213475204444817f)
#define SELF_RATIO 0.7978845608028654f   // (1/(2pi)^1.5) / (1/(4pi))
#define NEAR_R2 9.0f                 // erfc(3/sqrt2) ~ 2.7e-3, incoherent -> safe

__device__ __forceinline__ float rsqf(float a) {
    float r; asm("rsqrt.approx.f32 %0,%1;" : "=f"(r) : "f"(a)); return r;
}
__device__ __forceinline__ float rcpf(float a) {
    float r; asm("rcp.approx.f32 %0,%1;" : "=f"(r) : "f"(a)); return r;
}
__device__ __forceinline__ float exf(float a) {
    float r; asm("ex2.approx.f32 %0,%1;" : "=f"(r) : "f"(a)); return r;
}
// Full near-field kernel value erf(r/sqrt2)/r.
__device__ __forceinline__ float kern_corr(float r2, float rv) {
    const float r  = r2 * rv;
    const float tt = rcpf(fmaf(P3S, r, 1.0f));
    float h = fmaf(A3c, tt, A2c);
    h = fmaf(h, tt, A1c);
    const float u = (h * tt) * exf(r2 * NEG_HALF_LOG2E);
    return fmaf(-u, rv, rv);
}
// Correction delta: kern_corr(r2) - rv  (-> 0 when far)
__device__ __forceinline__ float corr_delta(float r2, float rv) {
    const float r  = r2 * rv;
    const float tt = rcpf(fmaf(P3S, r, 1.0f));
    float h = fmaf(A3c, tt, A2c);
    h = fmaf(h, tt, A1c);
    const float u = (h * tt) * exf(r2 * NEG_HALF_LOG2E);
    return -u * rv;
}

// ---------- Single pair kernel: IPT=2, per-lane masks, two-pass ----------
__global__ void __launch_bounds__(TPB)
ewald_pair_kernel(const float* __restrict__ pos, const float* __restrict__ q,
                  float* __restrict__ out) {
    __shared__ float4 sp[JC];   // {x, y, z, |p|^2}
    __shared__ float4 sb[JC];   // {b0, b1, b2, b3}

    const int t = threadIdx.x;
    const int tile  = blockIdx.x >> 1;
    const int chunk = blockIdx.x & 1;
    int I = 0, rem = tile;
    while (rem >= NTILES - I) { rem -= NTILES - I; I++; }
    const int J = I + rem;
    const bool diag = (I == J);

    const int jbase = J * TILE + chunk * JC;
    {   // 128 threads fill both smem arrays
        const int j = jbase + t;
        const float x = pos[3 * j + 0];
        const float y = pos[3 * j + 1];
        const float z = pos[3 * j + 2];
        sp[t] = make_float4(x, y, z, fmaf(x, x, fmaf(y, y, z * z)));
        sb[t] = ((const float4*)q)[j];
    }
    __syncthreads();

    // two i-points per thread: iA = base+t, iB = base+t+128
    const int iA = I * TILE + t;
    const int iB = iA + TPB;
    const float xA = pos[3 * iA + 0], yA = pos[3 * iA + 1], zA = pos[3 * iA + 2];
    const float xB = pos[3 * iB + 0], yB = pos[3 * iB + 1], zB = pos[3 * iB + 2];

    float accA0 = 0.f, accA1 = 0.f, accA2 = 0.f, accA3 = 0.f;
    float accB0 = 0.f, accB1 = 0.f, accB2 = 0.f, accB3 = 0.f;

    if (!diag) {
        const float nxA = -2.f * xA, nyA = -2.f * yA, nzA = -2.f * zA;
        const float nxB = -2.f * xB, nyB = -2.f * yB, nzB = -2.f * zB;
        const float sA = fmaf(xA, xA, fmaf(yA, yA, zA * zA));
        const float sB = fmaf(xB, xB, fmaf(yB, yB, zB * zB));

        for (int w = 0; w < 4; w++) {
            const int base = w * 32;
            unsigned mA = 0u, mB = 0u;
#pragma unroll
            for (int b = 0; b < 32; b++) {           // const shift index
                const float4 p = sp[base + b];
                const float4 c = sb[base + b];
                const float r2A = fmaf(p.x, nxA, fmaf(p.y, nyA, fmaf(p.z, nzA, p.w + sA)));
                const float r2B = fmaf(p.x, nxB, fmaf(p.y, nyB, fmaf(p.z, nzB, p.w + sB)));
                const float rvA = rsqf(r2A);
                const float rvB = rsqf(r2B);
                mA |= (r2A < NEAR_R2) ? (1u << b) : 0u;
                mB |= (r2B < NEAR_R2) ? (1u << b) : 0u;
                accA0 = fmaf(rvA, c.x, accA0);
                accA1 = fmaf(rvA, c.y, accA1);
                accA2 = fmaf(rvA, c.z, accA2);
                accA3 = fmaf(rvA, c.w, accA3);
                accB0 = fmaf(rvB, c.x, accB0);
                accB1 = fmaf(rvB, c.y, accB1);
                accB2 = fmaf(rvB, c.z, accB2);
                accB3 = fmaf(rvB, c.w, accB3);
            }
            while (mA) {                  // per-lane divergent, few bits
                const int bit = __ffs(mA) - 1;
                mA &= mA - 1u;
                const float4 p = sp[base + bit];
                const float4 c = sb[base + bit];
                const float r2 = fmaf(p.x, nxA, fmaf(p.y, nyA, fmaf(p.z, nzA, p.w + sA)));
                const float rv = rsqf(r2);
                const float d  = corr_delta(r2, rv);
                accA0 = fmaf(d, c.x, accA0);
                accA1 = fmaf(d, c.y, accA1);
                accA2 = fmaf(d, c.z, accA2);
                accA3 = fmaf(d, c.w, accA3);
            }
            while (mB) {
                const int bit = __ffs(mB) - 1;
                mB &= mB - 1u;
                const float4 p = sp[base + bit];
                const float4 c = sb[base + bit];
                const float r2 = fmaf(p.x, nxB, fmaf(p.y, nyB, fmaf(p.z, nzB, p.w + sB)));
                const float rv = rsqf(r2);
                const float d  = corr_delta(r2, rv);
                accB0 = fmaf(d, c.x, accB0);
                accB1 = fmaf(d, c.y, accB1);
                accB2 = fmaf(d, c.z, accB2);
                accB3 = fmaf(d, c.w, accB3);
            }
        }
    } else {
        // diagonal tile: exact diff-form + vote (64 CTAs only)
#pragma unroll 4
        for (int jj = 0; jj < JC; jj++) {
            const float4 p = sp[jj];
            const float4 c = sb[jj];
            const float dxA = p.x - xA, dyA = p.y - yA, dzA = p.z - zA;
            const float dxB = p.x - xB, dyB = p.y - yB, dzB = p.z - zB;
            const float r2A = fmaf(dxA, dxA, fmaf(dyA, dyA, dzA * dzA));
            const float r2B = fmaf(dxB, dxB, fmaf(dyB, dyB, dzB * dzB));
            const float rvA = rsqf(r2A);
            const float rvB = rsqf(r2B);
            float kA = rvA, kB = rvB;
            if (__any_sync(0xffffffffu, fminf(r2A, r2B) < NEAR_R2)) {
                kA = kern_corr(r2A, rvA);
                kB = kern_corr(r2B, rvB);
            }
            kA = (r2A > 0.f) ? kA : 0.f;      // exact-zero diagonal
            kB = (r2B > 0.f) ? kB : 0.f;
            accA0 = fmaf(kA, c.x, accA0);
            accA1 = fmaf(kA, c.y, accA1);
            accA2 = fmaf(kA, c.z, accA2);
            accA3 = fmaf(kA, c.w, accA3);
            accB0 = fmaf(kB, c.x, accB0);
            accB1 = fmaf(kB, c.y, accB1);
            accB2 = fmaf(kB, c.z, accB2);
            accB3 = fmaf(kB, c.w, accB3);
        }
    }

    // dot with i charges
    const float4 aA = ((const float4*)q)[iA];
    const float4 aB = ((const float4*)q)[iB];
    float s = fmaf(aA.x, accA0, fmaf(aA.y, accA1, fmaf(aA.z, accA2, aA.w * accA3)))
            + fmaf(aB.x, accB0, fmaf(aB.y, accB1, fmaf(aB.z, accB2, aB.w * accB3)));
    if (!diag) s = s + s;
    else if (chunk == 0) {
        const float qq = fmaf(aA.x, aA.x, fmaf(aA.y, aA.y, fmaf(aA.z, aA.z, aA.w * aA.w)))
                       + fmaf(aB.x, aB.x, fmaf(aB.y, aB.y, fmaf(aB.z, aB.z, aB.w * aB.w)));
        s = fmaf(SELF_RATIO, qq, s);
    }

    // deterministic in-block reduction (4 warps)
#pragma unroll
    for (int o = 16; o > 0; o >>= 1)
        s += __shfl_down_sync(0xffffffffu, s, o);

    __shared__ float red[TPB / 32];
    if ((t & 31) == 0) red[t >> 5] = s;
    __syncthreads();

    __shared__ bool is_last;
    if (t == 0) {
        g_partials[blockIdx.x] = (red[0] + red[1]) + (red[2] + red[3]);
        __threadfence();
        const unsigned int c = atomicAdd(&g_count, 1u);
        is_last = (c == NBLK - 1);
    }
    __syncthreads();

    // last CTA: fixed-order fp64 final reduction + scale
    if (is_last) {
        __threadfence();
        double d = 0.0;
        for (int u = t; u < NBLK; u += TPB) d += (double)g_partials[u];

        __shared__ double rs[TPB];
        rs[t] = d;
        __syncthreads();
#pragma unroll
        for (int o = TPB / 2; o > 0; o >>= 1) {
            if (t < o) rs[t] += rs[t + o];
            __syncthreads();
        }
        if (t == 0) {
            const double INV_4PI = 0.07957747154594767;
            out[0] = (float)(rs[0] * INV_4PI);
            g_count = 0;   // reset for next graph replay
        }
    }
}

extern "C" void kernel_launch(void* const* d_in, const int* in_sizes, int n_in,
                              void* d_out, int out_size) {
    const float* pos = (const float*)d_in[0];   // [8192,3] fp32
    const float* q   = (const float*)d_in[1];   // [8192,4] fp32
    float* out = (float*)d_out;                 // [1] fp32

    ewald_pair_kernel<<<NBLK, TPB>>>(pos, q, out);
}

// round 16
// speedup vs baseline: 1.0954x; 1.0954x over previous
#include <cuda_runtime.h>
#include <cuda_bf16.h>

// Fixed shapes from reference setup_inputs
#define NPTS 8192
#define TPB  256                     // 1 i-point per thread
#define TILE 256                     // i-tile edge
#define JC   64                      // j-chunk per CTA (4 chunks per tile)
#define NCHUNK (TILE / JC)           // 4
#define NTILES (NPTS / TILE)         // 32
#define NTRI (NTILES * (NTILES + 1) / 2)   // 528 triangular tiles
#define NBLK (NTRI * NCHUNK)         // 2112 CTAs

__device__ float g_partials[NBLK];
__device__ unsigned int g_count;     // zero at load; self-reset each launch

// A&S 7.1.25 (3-term, |eps| <= 2.5e-5), x = r/sqrt(2) folded into p
#define P3S  0.3326701f              // 0.47047 / sqrt(2)
#define A1c  0.3480242f
#define A2c  (-0.0958798f)
#define A3c  0.7478556f
#define NEG_HALF_LOG2E (-0.7213475204444817f)
#define SELF_RATIO 0.7978845608028654f   // (1/(2pi)^1.5) / (1/(4pi))
#define NEAR_R2 9.0f                 // erfc(3/sqrt2) ~ 2.7e-3, incoherent -> safe

__device__ __forceinline__ float rsqf(float a) {
    float r; asm("rsqrt.approx.f32 %0,%1;" : "=f"(r) : "f"(a)); return r;
}
__device__ __forceinline__ float rcpf(float a) {
    float r; asm("rcp.approx.f32 %0,%1;" : "=f"(r) : "f"(a)); return r;
}
__device__ __forceinline__ float exf(float a) {
    float r; asm("ex2.approx.f32 %0,%1;" : "=f"(r) : "f"(a)); return r;
}
// Full near-field kernel value erf(r/sqrt2)/r.
__device__ __forceinline__ float kern_corr(float r2, float rv) {
    const float r  = r2 * rv;
    const float tt = rcpf(fmaf(P3S, r, 1.0f));
    float h = fmaf(A3c, tt, A2c);
    h = fmaf(h, tt, A1c);
    const float u = (h * tt) * exf(r2 * NEG_HALF_LOG2E);
    return fmaf(-u, rv, rv);
}
// Correction delta: kern_corr(r2) - rv  (-> 0 when far)
__device__ __forceinline__ float corr_delta(float r2, float rv) {
    const float r  = r2 * rv;
    const float tt = rcpf(fmaf(P3S, r, 1.0f));
    float h = fmaf(A3c, tt, A2c);
    h = fmaf(h, tt, A1c);
    const float u = (h * tt) * exf(r2 * NEG_HALF_LOG2E);
    return -u * rv;
}

// ---------- Single pair kernel: per-lane mask (const-shift), two-pass ----------
__global__ void __launch_bounds__(TPB)
ewald_pair_kernel(const float* __restrict__ pos, const float* __restrict__ q,
                  float* __restrict__ out) {
    __shared__ float4 sp[JC];   // {x, y, z, |p|^2}
    __shared__ float4 sb[JC];   // {b0, b1, b2, b3}

    const int t = threadIdx.x;
    const int tile  = blockIdx.x >> 2;
    const int chunk = blockIdx.x & 3;
    int I = 0, rem = tile;
    while (rem >= NTILES - I) { rem -= NTILES - I; I++; }
    const int J = I + rem;
    const bool diag = (I == J);

    const int jbase = J * TILE + chunk * JC;
    if (t < JC) {                         // threads 0..63 fill both arrays
        const int j = jbase + t;
        const float x = pos[3 * j + 0];
        const float y = pos[3 * j + 1];
        const float z = pos[3 * j + 2];
        sp[t] = make_float4(x, y, z, fmaf(x, x, fmaf(y, y, z * z)));
        sb[t] = ((const float4*)q)[j];
    }
    __syncthreads();

    const int i0 = I * TILE + t;
    const float xi = pos[3 * i0 + 0];
    const float yi = pos[3 * i0 + 1];
    const float zi = pos[3 * i0 + 2];

    float acc0 = 0.f, acc1 = 0.f, acc2 = 0.f, acc3 = 0.f;

    if (!diag) {
        // dot-form r^2 = (si + sj) - 2 pi.pj
        const float nx2 = -2.f * xi, ny2 = -2.f * yi, nz2 = -2.f * zi;
        const float si  = fmaf(xi, xi, fmaf(yi, yi, zi * zi));

        // 2 words of 32 j each: pass 1 fully unrolled (const shifts),
        // pass 2 immediately on this word's register mask.
        for (int w = 0; w < JC / 32; w++) {
            const int base = w * 32;
            unsigned m = 0u;
#pragma unroll
            for (int b = 0; b < 32; b++) {           // b is compile-time const
                const float4 p = sp[base + b];
                const float r2 = fmaf(p.x, nx2, fmaf(p.y, ny2, fmaf(p.z, nz2, p.w + si)));
                const float rv = rsqf(r2);
                m |= (r2 < NEAR_R2) ? (1u << b) : 0u;   // one LOP, const shift
                const float4 c = sb[base + b];
                acc0 = fmaf(rv, c.x, acc0);
                acc1 = fmaf(rv, c.y, acc1);
                acc2 = fmaf(rv, c.z, acc2);
                acc3 = fmaf(rv, c.w, acc3);
            }
            while (m) {                   // per-lane divergent, ~0-1 bits/word
                const int bit = __ffs(m) - 1;
                m &= m - 1u;
                const int jj = base + bit;
                const float4 p = sp[jj];
                const float r2 = fmaf(p.x, nx2, fmaf(p.y, ny2, fmaf(p.z, nz2, p.w + si)));
                const float rv = rsqf(r2);
                const float d  = corr_delta(r2, rv);
                const float4 c = sb[jj];
                acc0 = fmaf(d, c.x, acc0);
                acc1 = fmaf(d, c.y, acc1);
                acc2 = fmaf(d, c.z, acc2);
                acc3 = fmaf(d, c.w, acc3);
            }
        }
    } else {
        // diagonal tile: exact diff-form + vote (128 CTAs only)
#pragma unroll 8
        for (int jj = 0; jj < JC; jj++) {
            const float4 p = sp[jj];
            const float dx = p.x - xi;
            const float dy = p.y - yi;
            const float dz = p.z - zi;
            const float r2 = fmaf(dx, dx, fmaf(dy, dy, dz * dz));
            const float rv = rsqf(r2);
            float k = rv;
            if (__any_sync(0xffffffffu, r2 < NEAR_R2))
                k = kern_corr(r2, rv);
            k = (r2 > 0.f) ? k : 0.f;         // exact-zero diagonal
            const float4 b = sb[jj];
            acc0 = fmaf(k, b.x, acc0);
            acc1 = fmaf(k, b.y, acc1);
            acc2 = fmaf(k, b.z, acc2);
            acc3 = fmaf(k, b.w, acc3);
        }
    }

    // dot with i charges
    const float4 a = ((const float4*)q)[i0];
    float s = fmaf(a.x, acc0, fmaf(a.y, acc1, fmaf(a.z, acc2, a.w * acc3)));
    if (!diag) s = s + s;
    else if (chunk == 0) {
        const float qq = fmaf(a.x, a.x, fmaf(a.y, a.y, fmaf(a.z, a.z, a.w * a.w)));
        s = fmaf(SELF_RATIO, qq, s);
    }

    // deterministic in-block reduction (8 warps)
#pragma unroll
    for (int o = 16; o > 0; o >>= 1)
        s += __shfl_down_sync(0xffffffffu, s, o);

    __shared__ float red[TPB / 32];
    if ((t & 31) == 0) red[t >> 5] = s;
    __syncthreads();

    __shared__ bool is_last;
    if (t == 0) {
        g_partials[blockIdx.x] = ((red[0] + red[1]) + (red[2] + red[3]))
                               + ((red[4] + red[5]) + (red[6] + red[7]));
        __threadfence();
        const unsigned int c = atomicAdd(&g_count, 1u);
        is_last = (c == NBLK - 1);
    }
    __syncthreads();

    // last CTA: fixed-order fp64 final reduction + scale
    if (is_last) {
        __threadfence();
        double d = 0.0;
        for (int u = t; u < NBLK; u += TPB) d += (double)g_partials[u];

        __shared__ double rs[TPB];
        rs[t] = d;
        __syncthreads();
#pragma unroll
        for (int o = TPB / 2; o > 0; o >>= 1) {
            if (t < o) rs[t] += rs[t + o];
            __syncthreads();
        }
        if (t == 0) {
            const double INV_4PI = 0.07957747154594767;
            out[0] = (float)(rs[0] * INV_4PI);
            g_count = 0;   // reset for next graph replay
        }
    }
}

extern "C" void kernel_launch(void* const* d_in, const int* in_sizes, int n_in,
                              void* d_out, int out_size) {
    const float* pos = (const float*)d_in[0];   // [8192,3] fp32
    const float* q   = (const float*)d_in[1];   // [8192,4] fp32
    float* out = (float*)d_out;                 // [1] fp32

    ewald_pair_kernel<<<NBLK, TPB>>>(pos, q, out);
}